// round 13
// baseline (speedup 1.0000x reference)
#include <cuda_runtime.h>
#include <math.h>

// ExpressionTree: out[b] = wr*tanh( (w1*sin(x_b·c1)+b1) * (w2*relu(x_b·c2)+b2) ) + br
// x: [B=131072, 1024] fp32, c1/c2: [1024] fp32, 6 scalar params, out: [B] fp32.
// HBM-bound: 512 MB read once @ ~8 TB/s -> ~64 us floor.
// Persistent grid-stride, warp-per-row, float4 coalesced, streaming (evict-first)
// x loads, coefficients held in registers (staged through shared once per block).

#define DDIM 1024
#define VEC4 (DDIM / 4)          // 256 float4 per row
#define WARPS_PER_BLOCK 8
#define THREADS (WARPS_PER_BLOCK * 32)
#define GRID_BLOCKS 304          // 152 SMs (GB300) x 2

__global__ __launch_bounds__(THREADS)
void expr_tree_kernel(const float4* __restrict__ x,
                      const float4* __restrict__ c1,
                      const float4* __restrict__ c2,
                      const float* __restrict__ pw1,
                      const float* __restrict__ pb1,
                      const float* __restrict__ pw2,
                      const float* __restrict__ pb2,
                      const float* __restrict__ pwr,
                      const float* __restrict__ pbr,
                      float* __restrict__ out,
                      int rows)
{
    __shared__ float4 sc1[VEC4];
    __shared__ float4 sc2[VEC4];

    const int tid  = threadIdx.x;
    const int lane = tid & 31;
    const int wid  = tid >> 5;

    // Stage coefficient vectors (8 KB) into shared once per block.
    // THREADS == VEC4 == 256: each thread loads exactly one float4 of each.
    sc1[tid] = c1[tid];
    sc2[tid] = c2[tid];
    __syncthreads();

    // Scalar params: read once, keep in registers.
    const float w1 = *pw1, b1 = *pb1;
    const float w2 = *pw2, b2 = *pb2;
    const float wr = *pwr, br = *pbr;

    const int warp_global = blockIdx.x * WARPS_PER_BLOCK + wid;
    const int total_warps = gridDim.x * WARPS_PER_BLOCK;

    // Per-lane coefficient slice is row-invariant: hoist into registers.
    const float4 a0 = sc1[0 * 32 + lane], g0 = sc2[0 * 32 + lane];
    const float4 a1 = sc1[1 * 32 + lane], g1 = sc2[1 * 32 + lane];
    const float4 a2 = sc1[2 * 32 + lane], g2 = sc2[2 * 32 + lane];
    const float4 a3 = sc1[3 * 32 + lane], g3 = sc2[3 * 32 + lane];
    const float4 a4 = sc1[4 * 32 + lane], g4 = sc2[4 * 32 + lane];
    const float4 a5 = sc1[5 * 32 + lane], g5 = sc2[5 * 32 + lane];
    const float4 a6 = sc1[6 * 32 + lane], g6 = sc2[6 * 32 + lane];
    const float4 a7 = sc1[7 * 32 + lane], g7 = sc2[7 * 32 + lane];

    for (int row = warp_global; row < rows; row += total_warps) {
        const float4* xr = x + (size_t)row * VEC4;

        // 8 independent streaming LDG.128 per lane, fully coalesced
        // (512B per warp per load; evict-first so the 512MB stream
        // doesn't churn L2).
        const float4 x0 = __ldcs(&xr[0 * 32 + lane]);
        const float4 x1 = __ldcs(&xr[1 * 32 + lane]);
        const float4 x2 = __ldcs(&xr[2 * 32 + lane]);
        const float4 x3 = __ldcs(&xr[3 * 32 + lane]);
        const float4 x4 = __ldcs(&xr[4 * 32 + lane]);
        const float4 x5 = __ldcs(&xr[5 * 32 + lane]);
        const float4 x6 = __ldcs(&xr[6 * 32 + lane]);
        const float4 x7 = __ldcs(&xr[7 * 32 + lane]);

        float acc1 = 0.0f, acc2 = 0.0f;
        #define ACC(xv, av, gv)                         \
            acc1 = fmaf(xv.x, av.x, acc1);              \
            acc1 = fmaf(xv.y, av.y, acc1);              \
            acc1 = fmaf(xv.z, av.z, acc1);              \
            acc1 = fmaf(xv.w, av.w, acc1);              \
            acc2 = fmaf(xv.x, gv.x, acc2);              \
            acc2 = fmaf(xv.y, gv.y, acc2);              \
            acc2 = fmaf(xv.z, gv.z, acc2);              \
            acc2 = fmaf(xv.w, gv.w, acc2);
        ACC(x0, a0, g0)
        ACC(x1, a1, g1)
        ACC(x2, a2, g2)
        ACC(x3, a3, g3)
        ACC(x4, a4, g4)
        ACC(x5, a5, g5)
        ACC(x6, a6, g6)
        ACC(x7, a7, g7)
        #undef ACC

        // Warp reduction (both sums together).
        #pragma unroll
        for (int off = 16; off > 0; off >>= 1) {
            acc1 += __shfl_xor_sync(0xffffffffu, acc1, off);
            acc2 += __shfl_xor_sync(0xffffffffu, acc2, off);
        }

        if (lane == 0) {
            const float u1 = fmaf(w1, sinf(acc1), b1);
            const float u2 = fmaf(w2, fmaxf(acc2, 0.0f), b2);
            out[row] = fmaf(wr, tanhf(u1 * u2), br);
        }
    }
}

extern "C" void kernel_launch(void* const* d_in, const int* in_sizes, int n_in,
                              void* d_out, int out_size)
{
    // metadata order: x, c1, c2, w1, b1, w2, b2, wr, br
    const float4* x  = (const float4*)d_in[0];
    const float4* c1 = (const float4*)d_in[1];
    const float4* c2 = (const float4*)d_in[2];
    const float* w1  = (const float*)d_in[3];
    const float* b1  = (const float*)d_in[4];
    const float* w2  = (const float*)d_in[5];
    const float* b2  = (const float*)d_in[6];
    const float* wr  = (const float*)d_in[7];
    const float* br  = (const float*)d_in[8];
    float* out = (float*)d_out;

    const int rows = out_size;  // B
    expr_tree_kernel<<<GRID_BLOCKS, THREADS>>>(x, c1, c2, w1, b1, w2, b2, wr, br,
                                               out, rows);
}

// round 15
// speedup vs baseline: 1.4142x; 1.4142x over previous
#include <cuda_runtime.h>
#include <math.h>

// ExpressionTree: out[b] = wr*tanh( (w1*sin(x_b·c1)+b1) * (w2*relu(x_b·c2)+b2) ) + br
// R13 post-mortem: regs=98 forced ptxas to serialize the 8 x-loads (MLP~2-4),
// leaving DRAM at 59.6%. Fix: coefficients read from shared in-loop (frees 64
// regs -> true 8-deep load MLP) + occupancy 16 -> 24 warps/SM.

#define DDIM 1024
#define VEC4 (DDIM / 4)          // 256 float4 per row
#define WARPS_PER_BLOCK 8
#define THREADS (WARPS_PER_BLOCK * 32)
#define BLOCKS_PER_SM 3
#define GRID_BLOCKS (152 * BLOCKS_PER_SM)   // 456 persistent blocks

__global__ __launch_bounds__(THREADS, BLOCKS_PER_SM)
void expr_tree_kernel(const float4* __restrict__ x,
                      const float4* __restrict__ c1,
                      const float4* __restrict__ c2,
                      const float* __restrict__ pw1,
                      const float* __restrict__ pb1,
                      const float* __restrict__ pw2,
                      const float* __restrict__ pb2,
                      const float* __restrict__ pwr,
                      const float* __restrict__ pbr,
                      float* __restrict__ out,
                      int rows)
{
    __shared__ float4 sc1[VEC4];
    __shared__ float4 sc2[VEC4];

    const int tid  = threadIdx.x;
    const int lane = tid & 31;
    const int wid  = tid >> 5;

    // Stage coefficient vectors (8 KB) into shared once per block.
    sc1[tid] = c1[tid];
    sc2[tid] = c2[tid];
    __syncthreads();

    // Scalar params in registers.
    const float w1 = *pw1, b1 = *pb1;
    const float w2 = *pw2, b2 = *pb2;
    const float wr = *pwr, br = *pbr;

    const int warp_global = blockIdx.x * WARPS_PER_BLOCK + wid;
    const int total_warps = gridDim.x * WARPS_PER_BLOCK;

    for (int row = warp_global; row < rows; row += total_warps) {
        const float4* xr = x + (size_t)row * VEC4;

        // 8 truly-concurrent streaming LDG.128 per lane (only ~32 regs of x
        // live; coeffs come from shared below, so ptxas keeps all 8 in flight).
        const float4 x0 = __ldcs(&xr[0 * 32 + lane]);
        const float4 x1 = __ldcs(&xr[1 * 32 + lane]);
        const float4 x2 = __ldcs(&xr[2 * 32 + lane]);
        const float4 x3 = __ldcs(&xr[3 * 32 + lane]);
        const float4 x4 = __ldcs(&xr[4 * 32 + lane]);
        const float4 x5 = __ldcs(&xr[5 * 32 + lane]);
        const float4 x6 = __ldcs(&xr[6 * 32 + lane]);
        const float4 x7 = __ldcs(&xr[7 * 32 + lane]);

        float acc1 = 0.0f, acc2 = 0.0f;
        // Coefficients from shared (LDS.128, conflict-free: 32 lanes x 16B
        // contiguous). Short-lived temps -> low register pressure.
        #define ACC(i, xv)                              \
        {                                               \
            const float4 av = sc1[(i) * 32 + lane];     \
            const float4 gv = sc2[(i) * 32 + lane];     \
            acc1 = fmaf(xv.x, av.x, acc1);              \
            acc1 = fmaf(xv.y, av.y, acc1);              \
            acc1 = fmaf(xv.z, av.z, acc1);              \
            acc1 = fmaf(xv.w, av.w, acc1);              \
            acc2 = fmaf(xv.x, gv.x, acc2);              \
            acc2 = fmaf(xv.y, gv.y, acc2);              \
            acc2 = fmaf(xv.z, gv.z, acc2);              \
            acc2 = fmaf(xv.w, gv.w, acc2);              \
        }
        ACC(0, x0)
        ACC(1, x1)
        ACC(2, x2)
        ACC(3, x3)
        ACC(4, x4)
        ACC(5, x5)
        ACC(6, x6)
        ACC(7, x7)
        #undef ACC

        // Warp reduction (both sums together).
        #pragma unroll
        for (int off = 16; off > 0; off >>= 1) {
            acc1 += __shfl_xor_sync(0xffffffffu, acc1, off);
            acc2 += __shfl_xor_sync(0xffffffffu, acc2, off);
        }

        if (lane == 0) {
            const float u1 = fmaf(w1, sinf(acc1), b1);
            const float u2 = fmaf(w2, fmaxf(acc2, 0.0f), b2);
            out[row] = fmaf(wr, tanhf(u1 * u2), br);
        }
    }
}

extern "C" void kernel_launch(void* const* d_in, const int* in_sizes, int n_in,
                              void* d_out, int out_size)
{
    // metadata order: x, c1, c2, w1, b1, w2, b2, wr, br
    const float4* x  = (const float4*)d_in[0];
    const float4* c1 = (const float4*)d_in[1];
    const float4* c2 = (const float4*)d_in[2];
    const float* w1  = (const float*)d_in[3];
    const float* b1  = (const float*)d_in[4];
    const float* w2  = (const float*)d_in[5];
    const float* b2  = (const float*)d_in[6];
    const float* wr  = (const float*)d_in[7];
    const float* br  = (const float*)d_in[8];
    float* out = (float*)d_out;

    const int rows = out_size;  // B
    expr_tree_kernel<<<GRID_BLOCKS, THREADS>>>(x, c1, c2, w1, b1, w2, b2, wr, br,
                                               out, rows);
}